// round 12
// baseline (speedup 1.0000x reference)
#include <cuda_runtime.h>
#include <math.h>
#include <stdint.h>

// Problem constants
#define B_ 256
#define R_ 1152
#define C_ 10
#define O_ 16
#define I_ 8
#define RT_ 4                 // r's per tile
#define RPC_ (R_/RT_)         // 288 tiles per c
#define NT_ (RPC_*C_)         // 2880 tiles total
#define G_ 444                // 148 SMs x 3 blocks (256 thr) -> one wave

// smem per buffer: W tile 128 float4 + x tile 2048 float4
#define WF4_ 128
#define XF4_ 2048
#define BUF_F4_ (WF4_ + XF4_)             // 2176 float4
#define SMEM_BYTES (2*BUF_F4_*16)         // 69632 B (x3 blocks = 209KB <= 228KB)

// ---------------- device scratch (no allocations allowed) ----------------
__device__ float g_xT[R_*B_*I_];       // x transposed: [r][b][i]
__device__ float g_Wp[R_*C_*I_*O_];    // W reformatted: [r][c][i][o]
__device__ float g_b1[R_*C_*B_];       // b1 logits, tiled: float2 @ (t*RT+rl)*128+bg
__device__ float g_S[C_*O_*B_];        // numerator accumulator: [c][o][b]
__device__ float g_E[C_*B_];           // softmax denominator:   [c][b]
__device__ float g_v[B_*C_*O_];        // squashed v: [b][c][o]

typedef unsigned long long u64;

// ---------------- packed f32x2 helpers ----------------
__device__ __forceinline__ u64 pk2(float lo, float hi){
    u64 r; asm("mov.b64 %0,{%1,%2};" : "=l"(r) : "f"(lo), "f"(hi)); return r;
}
__device__ __forceinline__ void upk2(u64 v, float& lo, float& hi){
    asm("mov.b64 {%0,%1},%2;" : "=f"(lo), "=f"(hi) : "l"(v));
}
__device__ __forceinline__ u64 ffma2(u64 a, u64 b, u64 c){
    u64 d; asm("fma.rn.f32x2 %0,%1,%2,%3;" : "=l"(d) : "l"(a), "l"(b), "l"(c)); return d;
}
__device__ __forceinline__ u64 fadd2(u64 a, u64 b){
    u64 d; asm("add.rn.f32x2 %0,%1,%2;" : "=l"(d) : "l"(a), "l"(b)); return d;
}

// ---------------- cp.async helpers ----------------
__device__ __forceinline__ void cp16(uint32_t s, const void* g){
    asm volatile("cp.async.ca.shared.global [%0], [%1], 16;" :: "r"(s), "l"(g));
}
#define CP_COMMIT() asm volatile("cp.async.commit_group;")
#define CP_WAIT0()  asm volatile("cp.async.wait_group 0;" ::: "memory")

// ---------------- combined prep kernel ----------------
#define XT_BLOCKS 288
#define PREP_BLOCKS (XT_BLOCKS + 720)

__global__ void __launch_bounds__(256) prep_kernel(const float* __restrict__ x,
                                                   const float* __restrict__ W){
    if (blockIdx.x < XT_BLOCKS){
        __shared__ __align__(16) float4 p0[32][33];
        __shared__ __align__(16) float4 p1[32][33];
        const int rt = blockIdx.x >> 3, bt = blockIdx.x & 7;
        const int r0 = rt*32, b0 = bt*32;
        const int w = threadIdx.x >> 5, lane = threadIdx.x & 31;
#pragma unroll
        for (int k = 0; k < 4; k++){
            int bl = w*4 + k;
            const float4* src = reinterpret_cast<const float4*>(
                x + ((b0+bl)*R_ + r0 + lane)*I_);
            p0[bl][lane] = src[0];
            p1[bl][lane] = src[1];
        }
        __syncthreads();
#pragma unroll
        for (int k = 0; k < 4; k++){
            int rl = w*4 + k;
            float4* dst = reinterpret_cast<float4*>(
                g_xT + ((r0+rl)*B_ + b0 + lane)*I_);
            dst[0] = p0[lane][rl];
            dst[1] = p1[lane][rl];
        }
    } else {
        int t = (blockIdx.x - XT_BLOCKS)*256 + threadIdx.x;
        int o = t % O_; int rc = t / O_;
        const float* src = W + t*I_;
        float* dst = g_Wp + rc*(I_*O_);
#pragma unroll
        for (int i = 0; i < I_; i++) dst[i*O_ + o] = src[i];
        if (t < C_*O_*B_) g_S[t] = 0.f;
        if (t < C_*B_)    g_E[t] = 0.f;
    }
}

// ---------------- fused routing pass ----------------
// 256 threads: tid = bg*2 + oh; bg in [0,128), oh in [0,2).
// Thread handles b_k = bg + 128k (k=0,1) and o in [oh*8, oh*8+8).
// MODE 0: S += u_hat
// MODE 1: b1 = <u,v0> (store float2, oh=0 only), S += e*u, E += e (oh=0 only)
// MODE 2: b2 = b1 + <u,v1>,                       S += e*u, E += e (oh=0 only)
template<int MODE>
__global__ void __launch_bounds__(256, 3) pass_kernel(){
    extern __shared__ __align__(16) float4 sm[];
    const int k_  = blockIdx.x;
    const int t0  = (k_    * NT_) / G_;
    const int t1  = ((k_+1)* NT_) / G_;
    const int tid = threadIdx.x;
    const int bg  = tid >> 1, oh = tid & 1;
    const float4* gW4 = reinterpret_cast<const float4*>(g_Wp);
    const float4* gX4 = reinterpret_cast<const float4*>(g_xT);

    uint32_t smbase = (uint32_t)__cvta_generic_to_shared(sm);

    // stage tile t into buffer p: W (128 f4, tid<128) + x (8 f4/thread)
    auto stage = [&](int t, int p){
        int c  = t / RPC_;
        int r0 = (t % RPC_) * RT_;
        uint32_t base = smbase + (uint32_t)p*BUF_F4_*16;
        if (tid < 128)
            cp16(base + tid*16, &gW4[((r0+(tid>>5))*C_ + c)*32 + (tid&31)]);
#pragma unroll
        for (int j = 0; j < 8; j++){
            int f  = tid + j*256;                  // [rl][h][b] layout
            int rl = f >> 9, rem = f & 511;
            int h  = rem >> 8, b = rem & 255;
            cp16(base + (WF4_ + f)*16, &gX4[(((r0+rl)*B_ + b) << 1) + h]);
        }
    };

    u64 u[8], S[8], v[8];
#pragma unroll
    for (int j = 0; j < 8; j++) S[j] = 0ull;
    float E[2] = {0.f, 0.f};
    int cur_c = -1;
    int p = 0;

    if (t0 < t1){ stage(t0, 0); CP_COMMIT(); }

#pragma unroll 1
    for (int t = t0; t < t1; t++){
        const int c  = t / RPC_;

        if (c != cur_c){
            if (cur_c >= 0){
#pragma unroll
                for (int k = 0; k < 2; k++){
                    int b = bg + 128*k;
#pragma unroll
                    for (int q = 0; q < 4; q++){
                        float lo, hi; upk2(S[k*4+q], lo, hi);
                        int o = oh*8 + 2*q;
                        atomicAdd(&g_S[(cur_c*O_ + o    )*B_ + b], lo);
                        atomicAdd(&g_S[(cur_c*O_ + o + 1)*B_ + b], hi);
                        S[k*4+q] = 0ull;
                    }
                    if (MODE && oh == 0){ atomicAdd(&g_E[cur_c*B_ + b], E[k]); E[k] = 0.f; }
                }
            }
            if (MODE){
#pragma unroll
                for (int k = 0; k < 2; k++){
                    const float4* vp = reinterpret_cast<const float4*>(
                        g_v + ((bg + 128*k)*C_ + c)*O_ + oh*8);
                    float4 f0 = vp[0], f1 = vp[1];
                    v[k*4+0] = pk2(f0.x, f0.y); v[k*4+1] = pk2(f0.z, f0.w);
                    v[k*4+2] = pk2(f1.x, f1.y); v[k*4+3] = pk2(f1.z, f1.w);
                }
            }
            cur_c = c;
        }

        CP_WAIT0();
        __syncthreads();
        if (t + 1 < t1){ stage(t+1, p^1); CP_COMMIT(); }

        // prefetch this tile's b1 (MODE 2): one float2 per rl (lane pairs broadcast)
        float2 bq[RT_];
        if (MODE == 2){
#pragma unroll
            for (int rl = 0; rl < RT_; rl++)
                bq[rl] = reinterpret_cast<const float2*>(g_b1)[(t*RT_ + rl)*128 + bg];
        }

        const float4* buf = sm + p*BUF_F4_;
        const float*  Wt  = reinterpret_cast<const float*>(buf);
        const float4* Xt  = buf + WF4_;

#pragma unroll
        for (int rl = 0; rl < RT_; rl++){
            float xs[2][8];
#pragma unroll
            for (int k = 0; k < 2; k++){
                int b = bg + 128*k;
                float4 h0 = Xt[rl*512 + b];
                float4 h1 = Xt[rl*512 + 256 + b];
                xs[k][0]=h0.x; xs[k][1]=h0.y; xs[k][2]=h0.z; xs[k][3]=h0.w;
                xs[k][4]=h1.x; xs[k][5]=h1.y; xs[k][6]=h1.z; xs[k][7]=h1.w;
            }

#pragma unroll
            for (int j = 0; j < 8; j++) u[j] = 0ull;
            const float* wrow = Wt + rl*128 + oh*8;
#pragma unroll
            for (int i = 0; i < I_; i++){
                const ulonglong2* wp = reinterpret_cast<const ulonglong2*>(wrow + i*16);
                ulonglong2 w0 = wp[0];           // o-pairs 0,1 of this half
                u64 w2 = wp[1].x, w3 = wp[1].y;  // o-pairs 2,3
#pragma unroll
                for (int k = 0; k < 2; k++){
                    u64 xd = pk2(xs[k][i], xs[k][i]);
                    u[k*4+0] = ffma2(w0.x, xd, u[k*4+0]);
                    u[k*4+1] = ffma2(w0.y, xd, u[k*4+1]);
                    u[k*4+2] = ffma2(w2,   xd, u[k*4+2]);
                    u[k*4+3] = ffma2(w3,   xd, u[k*4+3]);
                }
            }

            if (MODE == 0){
#pragma unroll
                for (int j = 0; j < 8; j++) S[j] = fadd2(S[j], u[j]);
            } else {
                float tk[2];
#pragma unroll
                for (int k = 0; k < 2; k++){
                    u64 qa = ffma2(u[k*4+0], v[k*4+0], 0ull);
                    u64 qb = ffma2(u[k*4+2], v[k*4+2], 0ull);
                    qa = ffma2(u[k*4+1], v[k*4+1], qa);
                    qb = ffma2(u[k*4+3], v[k*4+3], qb);
                    float lo, hi; upk2(fadd2(qa, qb), lo, hi);
                    float th = lo + hi;
                    tk[k] = th + __shfl_xor_sync(0xffffffffu, th, 1);
                }
                if (MODE == 2){
                    tk[0] += bq[rl].x; tk[1] += bq[rl].y;
                } else if (oh == 0){
                    reinterpret_cast<float2*>(g_b1)[(t*RT_ + rl)*128 + bg] =
                        make_float2(tk[0], tk[1]);
                }
#pragma unroll
                for (int k = 0; k < 2; k++){
                    float e = __expf(tk[k]);
                    if (oh == 0) E[k] += e;       // E counted ONCE per (b,r,c)
                    u64 ed = pk2(e, e);
                    S[k*4+0] = ffma2(u[k*4+0], ed, S[k*4+0]);
                    S[k*4+1] = ffma2(u[k*4+1], ed, S[k*4+1]);
                    S[k*4+2] = ffma2(u[k*4+2], ed, S[k*4+2]);
                    S[k*4+3] = ffma2(u[k*4+3], ed, S[k*4+3]);
                }
            }
        }
        p ^= 1;
    }

    if (cur_c >= 0){
#pragma unroll
        for (int k = 0; k < 2; k++){
            int b = bg + 128*k;
#pragma unroll
            for (int q = 0; q < 4; q++){
                float lo, hi; upk2(S[k*4+q], lo, hi);
                int o = oh*8 + 2*q;
                atomicAdd(&g_S[(cur_c*O_ + o    )*B_ + b], lo);
                atomicAdd(&g_S[(cur_c*O_ + o + 1)*B_ + b], hi);
            }
            if (MODE && oh == 0) atomicAdd(&g_E[cur_c*B_ + b], E[k]);
        }
    }
}

// ---------------- squash (+ normalization + accumulator re-zero) ----------------
__global__ void __launch_bounds__(128) squash_kernel(float* out, int mode){
    const int c = blockIdx.x;
    const int b = blockIdx.y*128 + threadIdx.x;

    float s[O_];
    float inv;
    if (mode){ inv = 1.0f / g_E[c*B_ + b]; g_E[c*B_ + b] = 0.f; }
    else     { inv = 1.0f / (float)R_; }

    float sq = 0.f;
#pragma unroll
    for (int o = 0; o < O_; o++){
        int sidx = (c*O_ + o)*B_ + b;
        float v = g_S[sidx] * inv;
        g_S[sidx] = 0.f;
        s[o] = v;
        sq += v*v;
    }

    float scale = sq / ((1.0f + sq) * sqrtf(sq + 1e-7f));
    float* dst = (out ? out : g_v) + (b*C_ + c)*O_;
    float4* d4 = reinterpret_cast<float4*>(dst);
#pragma unroll
    for (int q = 0; q < 4; q++)
        d4[q] = make_float4(s[4*q]*scale, s[4*q+1]*scale, s[4*q+2]*scale, s[4*q+3]*scale);
}

// ---------------- launch ----------------
extern "C" void kernel_launch(void* const* d_in, const int* in_sizes, int n_in,
                              void* d_out, int out_size){
    const float* x = (const float*)d_in[0];
    const float* W = (const float*)d_in[1];
    if (n_in >= 2 && in_sizes[0] == R_*C_*O_*I_){ const float* t = x; x = W; W = t; }

    cudaFuncSetAttribute(pass_kernel<0>, cudaFuncAttributeMaxDynamicSharedMemorySize, SMEM_BYTES);
    cudaFuncSetAttribute(pass_kernel<1>, cudaFuncAttributeMaxDynamicSharedMemorySize, SMEM_BYTES);
    cudaFuncSetAttribute(pass_kernel<2>, cudaFuncAttributeMaxDynamicSharedMemorySize, SMEM_BYTES);

    prep_kernel<<<PREP_BLOCKS, 256>>>(x, W);

    dim3 sq_grid(C_, 2);
    pass_kernel<0><<<G_, 256, SMEM_BYTES>>>();
    squash_kernel<<<sq_grid, 128>>>(nullptr, 0);          // v0
    pass_kernel<1><<<G_, 256, SMEM_BYTES>>>();
    squash_kernel<<<sq_grid, 128>>>(nullptr, 1);          // v1
    pass_kernel<2><<<G_, 256, SMEM_BYTES>>>();
    squash_kernel<<<sq_grid, 128>>>((float*)d_out, 1);    // v2 -> output (B,1,C,O,1)
}

// round 14
// speedup vs baseline: 1.1711x; 1.1711x over previous
#include <cuda_runtime.h>
#include <math.h>
#include <stdint.h>

// Problem constants
#define B_ 256
#define R_ 1152
#define C_ 10
#define O_ 16
#define I_ 8
#define RT_ 4                 // r's per tile
#define RPC_ (R_/RT_)         // 288 tiles per c
#define NT_ (RPC_*C_)         // 2880 tiles total
#define NM_ (NT_*RT_)         // 11520 rl-rows total (m-index, c-major: c = m/1152)
#define G_ 296                // 148 SMs x 2 blocks (256 thr) -> one wave
#define MAXROWS_ 40           // max rl-rows per block (10 tiles)

// ---------------- device scratch (no allocations allowed) ----------------
__device__ float g_xT[R_*B_*I_];       // x transposed: [r][b][i]
__device__ float g_Wp[R_*C_*I_*O_];    // W reformatted: [r][c][i][o]
__device__ float g_b1[R_*C_*B_];       // b1 logits: float2 @ m*128+bg  (m = rl-row)
__device__ float g_S[C_*O_*B_];        // numerator accumulator: [c][o][b]
__device__ float g_E[C_*B_];           // softmax denominator:   [c][b]
__device__ float g_v[B_*C_*O_];        // squashed v: [b][c][o]

typedef unsigned long long u64;

// ---------------- packed f32x2 helpers ----------------
__device__ __forceinline__ u64 pk2(float lo, float hi){
    u64 r; asm("mov.b64 %0,{%1,%2};" : "=l"(r) : "f"(lo), "f"(hi)); return r;
}
__device__ __forceinline__ void upk2(u64 v, float& lo, float& hi){
    asm("mov.b64 {%0,%1},%2;" : "=f"(lo), "=f"(hi) : "l"(v));
}
__device__ __forceinline__ u64 ffma2(u64 a, u64 b, u64 c){
    u64 d; asm("fma.rn.f32x2 %0,%1,%2,%3;" : "=l"(d) : "l"(a), "l"(b), "l"(c)); return d;
}
__device__ __forceinline__ u64 fadd2(u64 a, u64 b){
    u64 d; asm("add.rn.f32x2 %0,%1,%2;" : "=l"(d) : "l"(a), "l"(b)); return d;
}

// ---------------- cp.async helpers ----------------
__device__ __forceinline__ void cp16(uint32_t s, const void* g){
    asm volatile("cp.async.ca.shared.global [%0], [%1], 16;" :: "r"(s), "l"(g));
}
#define CP_COMMIT() asm volatile("cp.async.commit_group;")
#define CP_WAIT0()  asm volatile("cp.async.wait_group 0;" ::: "memory")

// ---------------- combined prep kernel ----------------
#define XT_BLOCKS 288
#define PREP_BLOCKS (XT_BLOCKS + 720)

__global__ void __launch_bounds__(256) prep_kernel(const float* __restrict__ x,
                                                   const float* __restrict__ W){
    if (blockIdx.x < XT_BLOCKS){
        __shared__ __align__(16) float4 p0[32][33];
        __shared__ __align__(16) float4 p1[32][33];
        const int rt = blockIdx.x >> 3, bt = blockIdx.x & 7;
        const int r0 = rt*32, b0 = bt*32;
        const int w = threadIdx.x >> 5, lane = threadIdx.x & 31;
#pragma unroll
        for (int k = 0; k < 4; k++){
            int bl = w*4 + k;
            const float4* src = reinterpret_cast<const float4*>(
                x + ((b0+bl)*R_ + r0 + lane)*I_);
            p0[bl][lane] = src[0];
            p1[bl][lane] = src[1];
        }
        __syncthreads();
#pragma unroll
        for (int k = 0; k < 4; k++){
            int rl = w*4 + k;
            float4* dst = reinterpret_cast<float4*>(
                g_xT + ((r0+rl)*B_ + b0 + lane)*I_);
            dst[0] = p0[lane][rl];
            dst[1] = p1[lane][rl];
        }
    } else {
        int t = (blockIdx.x - XT_BLOCKS)*256 + threadIdx.x;
        int o = t % O_; int rc = t / O_;
        const float* src = W + t*I_;
        float* dst = g_Wp + rc*(I_*O_);
#pragma unroll
        for (int i = 0; i < I_; i++) dst[i*O_ + o] = src[i];
        if (t < C_*O_*B_) g_S[t] = 0.f;
        if (t < C_*B_)    g_E[t] = 0.f;
    }
}

// ---------------- fused routing pass (barrier-free mainloop) ----------------
// 256 threads: tid = bg*2 + oh; bg in [0,128), oh in [0,2).
// Thread handles b_k = bg + 128k (k=0,1) and o in [oh*8, oh*8+8).
// Block stages ALL its W rows into smem once, then each warp free-runs over
// rl-rows m in [m0,m1) with NO further __syncthreads (W is read-only).
// m is c-major: c = m/1152, r = m%1152.
// MODE 0: S += u_hat
// MODE 1: b1 = <u,v0> (store float2, oh=0 only), S += e*u, E += e (oh=0 only)
// MODE 2: b2 = b1 + <u,v1>,                       S += e*u, E += e (oh=0 only)
template<int MODE>
__global__ void __launch_bounds__(256, 2) pass_kernel(){
    __shared__ __align__(16) float4 Wb[MAXROWS_*32];   // <= 20 KB
    const int k_  = blockIdx.x;
    const int m0  = ((k_    * NT_) / G_) * RT_;
    const int m1  = (((k_+1)* NT_) / G_) * RT_;
    const int tid = threadIdx.x;
    const int bg  = tid >> 1, oh = tid & 1;
    const float4* gW4 = reinterpret_cast<const float4*>(g_Wp);

    // ---- stage all W rows for [m0, m1) (one-time) ----
    uint32_t smbase = (uint32_t)__cvta_generic_to_shared(Wb);
    for (int idx = tid; idx < (m1 - m0)*32; idx += 256){
        int row = idx >> 5, w = idx & 31;
        int m = m0 + row;
        int c = m / 1152, r = m - c*1152;
        cp16(smbase + (uint32_t)idx*16, &gW4[(r*C_ + c)*32 + w]);
    }
    CP_COMMIT(); CP_WAIT0();
    __syncthreads();                 // the ONLY block-wide sync

    u64 u[8], S[8], v[8];
#pragma unroll
    for (int j = 0; j < 8; j++) S[j] = 0ull;
    float E[2] = {0.f, 0.f};
    int cur_c = -1;

    // x prefetch for m0
    float4 xa0, xa1, xb0, xb1;
    {
        int c = m0 / 1152, r = m0 - c*1152;
        const float4* pa = reinterpret_cast<const float4*>(g_xT + (r*B_ + bg)*I_);
        const float4* pb = reinterpret_cast<const float4*>(g_xT + (r*B_ + bg + 128)*I_);
        xa0 = pa[0]; xa1 = pa[1]; xb0 = pb[0]; xb1 = pb[1];
    }

#pragma unroll 1
    for (int m = m0; m < m1; m++){
        const int c = m / 1152;

        if (c != cur_c){
            if (cur_c >= 0){
#pragma unroll
                for (int k = 0; k < 2; k++){
                    int b = bg + 128*k;
#pragma unroll
                    for (int q = 0; q < 4; q++){
                        float lo, hi; upk2(S[k*4+q], lo, hi);
                        int o = oh*8 + 2*q;
                        atomicAdd(&g_S[(cur_c*O_ + o    )*B_ + b], lo);
                        atomicAdd(&g_S[(cur_c*O_ + o + 1)*B_ + b], hi);
                        S[k*4+q] = 0ull;
                    }
                    if (MODE && oh == 0){ atomicAdd(&g_E[cur_c*B_ + b], E[k]); E[k] = 0.f; }
                }
            }
            if (MODE){
#pragma unroll
                for (int k = 0; k < 2; k++){
                    const float4* vp = reinterpret_cast<const float4*>(
                        g_v + ((bg + 128*k)*C_ + c)*O_ + oh*8);
                    float4 f0 = vp[0], f1 = vp[1];
                    v[k*4+0] = pk2(f0.x, f0.y); v[k*4+1] = pk2(f0.z, f0.w);
                    v[k*4+2] = pk2(f1.x, f1.y); v[k*4+3] = pk2(f1.z, f1.w);
                }
            }
            cur_c = c;
        }

        // issue b1 load early (MODE 2) so latency hides under the u-phase
        float2 bq;
        if (MODE == 2) bq = reinterpret_cast<const float2*>(g_b1)[m*128 + bg];

        // unpack current x, then prefetch next row's x (m+1 address is safe at m1 edge)
        const float xsa[8] = {xa0.x, xa0.y, xa0.z, xa0.w, xa1.x, xa1.y, xa1.z, xa1.w};
        const float xsb[8] = {xb0.x, xb0.y, xb0.z, xb0.w, xb1.x, xb1.y, xb1.z, xb1.w};
        {
            int mn = m + 1; if (mn >= NM_) mn = 0;
            int cn = mn / 1152, rn = mn - cn*1152;
            const float4* pa = reinterpret_cast<const float4*>(g_xT + (rn*B_ + bg)*I_);
            const float4* pb = reinterpret_cast<const float4*>(g_xT + (rn*B_ + bg + 128)*I_);
            xa0 = pa[0]; xa1 = pa[1]; xb0 = pb[0]; xb1 = pb[1];
        }

#pragma unroll
        for (int j = 0; j < 8; j++) u[j] = 0ull;
        const float* wrow = reinterpret_cast<const float*>(Wb + (m - m0)*32) + oh*8;
#pragma unroll
        for (int i = 0; i < I_; i++){
            const ulonglong2* wp = reinterpret_cast<const ulonglong2*>(wrow + i*16);
            ulonglong2 w0 = wp[0];           // o-pairs 0,1 of this half
            u64 w2 = wp[1].x, w3 = wp[1].y;  // o-pairs 2,3
            u64 xda = pk2(xsa[i], xsa[i]);
            u64 xdb = pk2(xsb[i], xsb[i]);
            u[0] = ffma2(w0.x, xda, u[0]);
            u[1] = ffma2(w0.y, xda, u[1]);
            u[2] = ffma2(w2,   xda, u[2]);
            u[3] = ffma2(w3,   xda, u[3]);
            u[4] = ffma2(w0.x, xdb, u[4]);
            u[5] = ffma2(w0.y, xdb, u[5]);
            u[6] = ffma2(w2,   xdb, u[6]);
            u[7] = ffma2(w3,   xdb, u[7]);
        }

        if (MODE == 0){
#pragma unroll
            for (int j = 0; j < 8; j++) S[j] = fadd2(S[j], u[j]);
        } else {
            float tk[2];
#pragma unroll
            for (int k = 0; k < 2; k++){
                u64 qa = ffma2(u[k*4+0], v[k*4+0], 0ull);
                u64 qb = ffma2(u[k*4+2], v[k*4+2], 0ull);
                qa = ffma2(u[k*4+1], v[k*4+1], qa);
                qb = ffma2(u[k*4+3], v[k*4+3], qb);
                float lo, hi; upk2(fadd2(qa, qb), lo, hi);
                float th = lo + hi;
                tk[k] = th + __shfl_xor_sync(0xffffffffu, th, 1);
            }
            if (MODE == 2){
                tk[0] += bq.x; tk[1] += bq.y;
            } else if (oh == 0){
                reinterpret_cast<float2*>(g_b1)[m*128 + bg] = make_float2(tk[0], tk[1]);
            }
#pragma unroll
            for (int k = 0; k < 2; k++){
                float e = __expf(tk[k]);
                if (oh == 0) E[k] += e;          // E counted ONCE per (b,r,c)
                u64 ed = pk2(e, e);
                S[k*4+0] = ffma2(u[k*4+0], ed, S[k*4+0]);
                S[k*4+1] = ffma2(u[k*4+1], ed, S[k*4+1]);
                S[k*4+2] = ffma2(u[k*4+2], ed, S[k*4+2]);
                S[k*4+3] = ffma2(u[k*4+3], ed, S[k*4+3]);
            }
        }
    }

    if (cur_c >= 0){
#pragma unroll
        for (int k = 0; k < 2; k++){
            int b = bg + 128*k;
#pragma unroll
            for (int q = 0; q < 4; q++){
                float lo, hi; upk2(S[k*4+q], lo, hi);
                int o = oh*8 + 2*q;
                atomicAdd(&g_S[(cur_c*O_ + o    )*B_ + b], lo);
                atomicAdd(&g_S[(cur_c*O_ + o + 1)*B_ + b], hi);
            }
            if (MODE && oh == 0) atomicAdd(&g_E[cur_c*B_ + b], E[k]);
        }
    }
}

// ---------------- squash (+ normalization + accumulator re-zero) ----------------
__global__ void __launch_bounds__(128) squash_kernel(float* out, int mode){
    const int c = blockIdx.x;
    const int b = blockIdx.y*128 + threadIdx.x;

    float s[O_];
    float inv;
    if (mode){ inv = 1.0f / g_E[c*B_ + b]; g_E[c*B_ + b] = 0.f; }
    else     { inv = 1.0f / (float)R_; }

    float sq = 0.f;
#pragma unroll
    for (int o = 0; o < O_; o++){
        int sidx = (c*O_ + o)*B_ + b;
        float v = g_S[sidx] * inv;
        g_S[sidx] = 0.f;
        s[o] = v;
        sq += v*v;
    }

    float scale = sq / ((1.0f + sq) * sqrtf(sq + 1e-7f));
    float* dst = (out ? out : g_v) + (b*C_ + c)*O_;
    float4* d4 = reinterpret_cast<float4*>(dst);
#pragma unroll
    for (int q = 0; q < 4; q++)
        d4[q] = make_float4(s[4*q]*scale, s[4*q+1]*scale, s[4*q+2]*scale, s[4*q+3]*scale);
}

// ---------------- launch ----------------
extern "C" void kernel_launch(void* const* d_in, const int* in_sizes, int n_in,
                              void* d_out, int out_size){
    const float* x = (const float*)d_in[0];
    const float* W = (const float*)d_in[1];
    if (n_in >= 2 && in_sizes[0] == R_*C_*O_*I_){ const float* t = x; x = W; W = t; }

    prep_kernel<<<PREP_BLOCKS, 256>>>(x, W);

    dim3 sq_grid(C_, 2);
    pass_kernel<0><<<G_, 256>>>();
    squash_kernel<<<sq_grid, 128>>>(nullptr, 0);          // v0
    pass_kernel<1><<<G_, 256>>>();
    squash_kernel<<<sq_grid, 128>>>(nullptr, 1);          // v1
    pass_kernel<2><<<G_, 256>>>();
    squash_kernel<<<sq_grid, 128>>>((float*)d_out, 1);    // v2 -> output (B,1,C,O,1)
}